// round 14
// baseline (speedup 1.0000x reference)
#include <cuda_runtime.h>
#include <cuda_bf16.h>
#include <cstdint>

#define D        256
#define KCODES   8192
#define NTOK     32768
#define CTAM     128
#define CTAN     128
#define NTILES   (NTOK / CTAM)       // 256
#define NCHUNKS  (KCODES / CTAN)     // 64
#define NSPLIT   4
#define CPS      (NCHUNKS / NSPLIT)  // 16
#define CAP      64
#define WINDOW   5.0e-4f
#define GBLOCKS  (NTOK / 8)
#define ZQ_ELEMS ((size_t)NTOK * D)
#define OUT_FULL (ZQ_ELEMS + 3 + NTOK)

// smem layout (bytes): padded bf16 rows, 264 elems = 528B (4-bank rotation)
#define SROW     528
#define ZS_BYTES (CTAM * SROW)                   // 67584
#define ES_OFF(b)  (ZS_BYTES + (b) * ZS_BYTES)   // two e buffers
#define ESQ_OFF(b) (3 * ZS_BYTES + (b) * 512)
#define SMEM_TOTAL (3 * ZS_BYTES + 1024)         // 203776

// ---- scratch (__device__ globals: sanctioned no-alloc path) ----
__device__ float          g_esq[KCODES];
__device__ float          g_zsq[NTOK];
__device__ unsigned short g_zbf[(size_t)NTOK * D];    // bf16 row-major
__device__ unsigned short g_ebf[(size_t)KCODES * D];  // bf16 row-major
__device__ int            g_ccount[NTOK];
__device__ int            g_cand[(size_t)NTOK * CAP];
__device__ int            g_bidx[NTOK];
__device__ float          g_part[GBLOCKS];

// ============================================================
// PTX helpers (baseline sm_80-level ISA only)
// ============================================================
__device__ __forceinline__ uint32_t smem_u32(const void* p) {
    uint32_t a;
    asm("{ .reg .u64 t; cvta.to.shared.u64 t, %1; cvt.u32.u64 %0, t; }" : "=r"(a) : "l"(p));
    return a;
}
__device__ __forceinline__ void cpa16(uint32_t dst, const void* src) {
    asm volatile("cp.async.cg.shared.global [%0], [%1], 16;" :: "r"(dst), "l"(src));
}
#define CP_COMMIT() asm volatile("cp.async.commit_group;" ::: "memory")
#define CP_WAIT0()  asm volatile("cp.async.wait_group 0;" ::: "memory")

__device__ __forceinline__ void ldsm4(uint32_t& r0, uint32_t& r1, uint32_t& r2, uint32_t& r3,
                                      uint32_t addr) {
    asm volatile("ldmatrix.sync.aligned.m8n8.x4.shared.b16 {%0,%1,%2,%3}, [%4];"
                 : "=r"(r0), "=r"(r1), "=r"(r2), "=r"(r3) : "r"(addr));
}
__device__ __forceinline__ void mma_bf16(float& c0, float& c1, float& c2, float& c3,
                                         uint32_t a0, uint32_t a1, uint32_t a2, uint32_t a3,
                                         uint32_t b0, uint32_t b1) {
    asm volatile("mma.sync.aligned.m16n8k16.row.col.f32.bf16.bf16.f32 "
                 "{%0,%1,%2,%3}, {%4,%5,%6,%7}, {%8,%9}, {%0,%1,%2,%3};"
                 : "+f"(c0), "+f"(c1), "+f"(c2), "+f"(c3)
                 : "r"(a0), "r"(a1), "r"(a2), "r"(a3), "r"(b0), "r"(b1));
}
__device__ __forceinline__ uint32_t pack_bf(float lo, float hi) {
    __nv_bfloat162 v = __floats2bfloat162_rn(lo, hi);
    return *reinterpret_cast<uint32_t*>(&v);
}

// ============================================================
// Kernel 0a: per-code ||e||^2 (bit-critical sequential chain)
//            FUSED with bf16 row conversion (same loads)
// ============================================================
__global__ void esq_kernel(const float* __restrict__ emb) {
    int k = blockIdx.x * blockDim.x + threadIdx.x;
    if (k >= KCODES) return;
    const float4* row = reinterpret_cast<const float4*>(emb + (size_t)k * D);
    uint4* dst = reinterpret_cast<uint4*>(g_ebf + (size_t)k * D);
    float s = 0.f;
#pragma unroll
    for (int i = 0; i < D / 8; ++i) {
        float4 a = row[2 * i];
        float4 b = row[2 * i + 1];
        s = fmaf(a.x, a.x, s); s = fmaf(a.y, a.y, s);
        s = fmaf(a.z, a.z, s); s = fmaf(a.w, a.w, s);
        s = fmaf(b.x, b.x, s); s = fmaf(b.y, b.y, s);
        s = fmaf(b.z, b.z, s); s = fmaf(b.w, b.w, s);
        dst[i] = make_uint4(pack_bf(a.x, a.y), pack_bf(a.z, a.w),
                            pack_bf(b.x, b.y), pack_bf(b.z, b.w));
    }
    g_esq[k] = s;
}

// ============================================================
// Kernel 0b: per-token ||z||^2 (bit-critical chain)
//            FUSED with bf16 row conversion + ccount zeroing
// ============================================================
__global__ void zsq_kernel(const float* __restrict__ z) {
    int n = blockIdx.x * blockDim.x + threadIdx.x;
    if (n >= NTOK) return;
    g_ccount[n] = 0;
    const float4* row = reinterpret_cast<const float4*>(z + (size_t)n * D);
    uint4* dst = reinterpret_cast<uint4*>(g_zbf + (size_t)n * D);
    float s = 0.f;
#pragma unroll 4
    for (int i = 0; i < D / 8; ++i) {
        float4 a = row[2 * i];
        float4 b = row[2 * i + 1];
        s = fmaf(a.x, a.x, s); s = fmaf(a.y, a.y, s);
        s = fmaf(a.z, a.z, s); s = fmaf(a.w, a.w, s);
        s = fmaf(b.x, b.x, s); s = fmaf(b.y, b.y, s);
        s = fmaf(b.z, b.z, s); s = fmaf(b.w, b.w, s);
        dst[i] = make_uint4(pack_bf(a.x, a.y), pack_bf(a.z, a.w),
                            pack_bf(b.x, b.y), pack_bf(b.z, b.w));
    }
    g_zsq[n] = s;
}

// ============================================================
// Kernel 1: bf16 mma.sync GEMM + running-min candidate filter.
//   EXACT R6/R11-validated shape (do not touch).
// ============================================================
__global__ __launch_bounds__(256, 1)
void filter_kernel() {
    extern __shared__ char smc[];
    const uint32_t sb = smem_u32(smc);
    const int tid = threadIdx.x, wid = tid >> 5, lane = tid & 31;
    const int tile = blockIdx.x >> 2;
    const int sp   = blockIdx.x & 3;
    const int g = lane >> 2, t4 = lane & 3;

    // ---- stage z tile + chunk 0 (+esq) via cp.async ----
    {
        const char* zsrc = (const char*)(g_zbf + (size_t)tile * CTAM * D);
#pragma unroll 4
        for (int i = tid; i < 4096; i += 256) {
            int r = i >> 5, c = i & 31;
            cpa16(sb + r * SROW + c * 16, zsrc + r * 512 + c * 16);
        }
        int chunk0 = sp * CPS;
        const char* esrc = (const char*)(g_ebf + (size_t)chunk0 * CTAN * D);
#pragma unroll 4
        for (int i = tid; i < 4096; i += 256) {
            int r = i >> 5, c = i & 31;
            cpa16(sb + ES_OFF(0) + r * SROW + c * 16, esrc + r * 512 + c * 16);
        }
        if (tid < 32) cpa16(sb + ESQ_OFF(0) + tid * 16,
                            (const char*)(g_esq + chunk0 * CTAN) + tid * 16);
        CP_COMMIT();
    }

    // per-lane fragment address bases (validated mapping)
    const uint32_t aBase = sb + (uint32_t)(wid * 16 + (lane & 15)) * SROW
                              + (uint32_t)((lane >> 4) * 8) * 2;
    const uint32_t bRowOff = (uint32_t)((lane & 7) + ((lane & 16) ? 8 : 0)) * SROW
                           + (uint32_t)((lane & 8) ? 8 : 0) * 2;

    const int tokg  = tile * CTAM + wid * 16 + g;
    const float zq0 = g_zsq[tokg];
    const float zq1 = g_zsq[tokg + 8];
    float run0 = 3.4e38f, run1 = 3.4e38f;

    for (int cl = 0; cl < CPS; ++cl) {
        const int cur = cl & 1;
        CP_WAIT0();
        __syncthreads();
        if (cl + 1 < CPS) {
            const int nxt = sp * CPS + cl + 1;
            const char* esrc = (const char*)(g_ebf + (size_t)nxt * CTAN * D);
#pragma unroll 4
            for (int i = tid; i < 4096; i += 256) {
                int r = i >> 5, c = i & 31;
                cpa16(sb + ES_OFF(1 - cur) + r * SROW + c * 16, esrc + r * 512 + c * 16);
            }
            if (tid < 32) cpa16(sb + ESQ_OFF(1 - cur) + tid * 16,
                                (const char*)(g_esq + nxt * CTAN) + tid * 16);
            CP_COMMIT();
        }

        float acc[16][4];
#pragma unroll
        for (int nb = 0; nb < 16; ++nb)
#pragma unroll
            for (int q = 0; q < 4; ++q) acc[nb][q] = 0.f;

        const uint32_t bBase = sb + ES_OFF(cur) + bRowOff;
#pragma unroll
        for (int ks = 0; ks < 16; ++ks) {
            uint32_t a0, a1, a2, a3;
            ldsm4(a0, a1, a2, a3, aBase + ks * 32);
#pragma unroll
            for (int nbp = 0; nbp < 8; ++nbp) {
                uint32_t b0, b1, b2, b3;
                ldsm4(b0, b1, b2, b3, bBase + nbp * (16 * SROW) + ks * 32);
                mma_bf16(acc[2 * nbp][0], acc[2 * nbp][1], acc[2 * nbp][2], acc[2 * nbp][3],
                         a0, a1, a2, a3, b0, b1);
                mma_bf16(acc[2 * nbp + 1][0], acc[2 * nbp + 1][1], acc[2 * nbp + 1][2], acc[2 * nbp + 1][3],
                         a0, a1, a2, a3, b2, b3);
            }
        }

        // ---- epilogue: approx scores, chunk-min, running-min, collect ----
        const int chunk = sp * CPS + cl;
        const int code0 = chunk * CTAN;
        const float* esqs = reinterpret_cast<const float*>(smc + ESQ_OFF(cur));
        float m0 = 3.4e38f, m1 = 3.4e38f;
#pragma unroll
        for (int nb = 0; nb < 16; ++nb) {
            float2 ee = *reinterpret_cast<const float2*>(esqs + nb * 8 + 2 * t4);
            float s00 = fmaf(-2.f, acc[nb][0], zq0 + ee.x);
            float s01 = fmaf(-2.f, acc[nb][1], zq0 + ee.y);
            float s10 = fmaf(-2.f, acc[nb][2], zq1 + ee.x);
            float s11 = fmaf(-2.f, acc[nb][3], zq1 + ee.y);
            acc[nb][0] = s00; acc[nb][1] = s01; acc[nb][2] = s10; acc[nb][3] = s11;
            m0 = fminf(m0, fminf(s00, s01));
            m1 = fminf(m1, fminf(s10, s11));
        }
        // quad-reduce (lanes sharing g)
        m0 = fminf(m0, __shfl_xor_sync(0xffffffffu, m0, 1));
        m0 = fminf(m0, __shfl_xor_sync(0xffffffffu, m0, 2));
        m1 = fminf(m1, __shfl_xor_sync(0xffffffffu, m1, 1));
        m1 = fminf(m1, __shfl_xor_sync(0xffffffffu, m1, 2));
        run0 = fminf(run0, m0);
        run1 = fminf(run1, m1);
        const float thr0 = run0 + WINDOW, thr1 = run1 + WINDOW;

#pragma unroll
        for (int nb = 0; nb < 16; ++nb) {
            const int cb = code0 + nb * 8 + 2 * t4;
            if (acc[nb][0] <= thr0) {
                int p = atomicAdd(&g_ccount[tokg], 1);
                if (p < CAP) g_cand[(size_t)tokg * CAP + p] = cb;
            }
            if (acc[nb][1] <= thr0) {
                int p = atomicAdd(&g_ccount[tokg], 1);
                if (p < CAP) g_cand[(size_t)tokg * CAP + p] = cb + 1;
            }
            if (acc[nb][2] <= thr1) {
                int p = atomicAdd(&g_ccount[tokg + 8], 1);
                if (p < CAP) g_cand[(size_t)(tokg + 8) * CAP + p] = cb;
            }
            if (acc[nb][3] <= thr1) {
                int p = atomicAdd(&g_ccount[tokg + 8], 1);
                if (p < CAP) g_cand[(size_t)(tokg + 8) * CAP + p] = cb + 1;
            }
        }
        __syncthreads();   // all warps done with buf[cur] before it is refilled
    }
}

// ============================================================
// Kernel 2: exact rescore of candidates — bit-exact quantized score,
//   lexicographic (value, index) min = reference argmin.
//   REBUILT: cnt==1 fast path; fallback demoted to unroll-1 scalar
//   loop; launch_bounds(256,4) caps regs (was 255 -> 10% occ).
// ============================================================
__global__ __launch_bounds__(256, 4)
void rescore_kernel(const float* __restrict__ z, const float* __restrict__ emb) {
    const int w = (blockIdx.x << 3) + (threadIdx.x >> 5);
    const int lane = threadIdx.x & 31;
    const int cnt = g_ccount[w];

    // fast path: single candidate IS the argmin (no scoring needed)
    if (cnt == 1) {
        if (lane == 0) g_bidx[w] = g_cand[(size_t)w * CAP];
        return;
    }

    const float4* zr = reinterpret_cast<const float4*>(z + (size_t)w * D);
    const float zq = g_zsq[w];
    float bs = 3.4e38f; int bi = 0x7fffffff;

    if (cnt > 0 && cnt <= CAP) {
        for (int j = lane; j < cnt; j += 32) {
            int code = g_cand[(size_t)w * CAP + j];
            const float4* er = reinterpret_cast<const float4*>(emb + (size_t)code * D);
            float acc = 0.f;
#pragma unroll
            for (int i = 0; i < D / 4; ++i) {
                float4 a = zr[i], b = er[i];
                acc = fmaf(a.x, b.x, acc); acc = fmaf(a.y, b.y, acc);
                acc = fmaf(a.z, b.z, acc); acc = fmaf(a.w, b.w, acc);
            }
            float t1 = __fadd_rn(zq, g_esq[code]);
            float s  = __fadd_rn(t1, -2.0f * acc);
            if (s < bs || (s == bs && code < bi)) { bs = s; bi = code; }
        }
    } else {
        // overflow fallback (never observed): simple scalar loop, low regs
#pragma unroll 1
        for (int code = lane; code < KCODES; code += 32) {
            const float4* er = reinterpret_cast<const float4*>(emb + (size_t)code * D);
            float acc = 0.f;
#pragma unroll 8
            for (int i = 0; i < D / 4; ++i) {
                float4 a = zr[i], b = er[i];
                acc = fmaf(a.x, b.x, acc); acc = fmaf(a.y, b.y, acc);
                acc = fmaf(a.z, b.z, acc); acc = fmaf(a.w, b.w, acc);
            }
            float t1 = __fadd_rn(zq, g_esq[code]);
            float s  = __fadd_rn(t1, -2.0f * acc);
            if (s < bs) { bs = s; bi = code; }   // ascending codes: first-min kept
        }
    }
#pragma unroll
    for (int m = 16; m >= 1; m >>= 1) {
        float ov = __shfl_xor_sync(0xffffffffu, bs, m);
        int   oi = __shfl_xor_sync(0xffffffffu, bi, m);
        if (ov < bs || (ov == bs && oi < bi)) { bs = ov; bi = oi; }
    }
    if (lane == 0) g_bidx[w] = bi;
}

// ============================================================
// Kernel 3: gather + straight-through output + loss partials
//   exact replication of fl(z + fl(e - z))
// ============================================================
__global__ void gather_kernel(const float* __restrict__ z, const float* __restrict__ emb,
                              float* __restrict__ out, int out_size) {
    __shared__ float wsum[8];
    const int lane = threadIdx.x & 31;
    const int wib  = threadIdx.x >> 5;
    const int n    = blockIdx.x * 8 + wib;

    const int idx = g_bidx[n];
    const float4* zr = reinterpret_cast<const float4*>(z   + (size_t)n   * D);
    const float4* er = reinterpret_cast<const float4*>(emb + (size_t)idx * D);
    float4* orow = reinterpret_cast<float4*>(out + (size_t)n * D);

    float ss = 0.f;
#pragma unroll
    for (int i = lane; i < D / 4; i += 32) {
        float4 zv = zr[i], ev = er[i], df, ov;
        df.x = ev.x - zv.x; df.y = ev.y - zv.y; df.z = ev.z - zv.z; df.w = ev.w - zv.w;
        ov.x = zv.x + df.x; ov.y = zv.y + df.y; ov.z = zv.z + df.z; ov.w = zv.w + df.w;
        ss = fmaf(df.x, df.x, ss); ss = fmaf(df.y, df.y, ss);
        ss = fmaf(df.z, df.z, ss); ss = fmaf(df.w, df.w, ss);
        if ((size_t)out_size >= ZQ_ELEMS) orow[i] = ov;
    }
#pragma unroll
    for (int m = 16; m >= 1; m >>= 1) ss += __shfl_xor_sync(0xffffffffu, ss, m);
    if (lane == 0) wsum[wib] = ss;
    __syncthreads();
    if (threadIdx.x == 0) {
        float t = 0.f;
#pragma unroll
        for (int w = 0; w < 8; ++w) t += wsum[w];
        g_part[blockIdx.x] = t;
    }
    if (lane == 0 && (size_t)out_size >= OUT_FULL)
        out[ZQ_ELEMS + 3 + n] = (float)idx;
}

// ============================================================
// Kernel 4: deterministic loss finalize (double accumulation)
// ============================================================
__global__ void loss_kernel(float* __restrict__ out, int out_size) {
    __shared__ double sh[256];
    const int t = threadIdx.x;
    double s = 0.0;
#pragma unroll 4
    for (int i = t * (GBLOCKS / 256); i < (t + 1) * (GBLOCKS / 256); ++i)
        s += (double)g_part[i];
    sh[t] = s;
    __syncthreads();
    for (int m = 128; m >= 1; m >>= 1) {
        if (t < m) sh[t] += sh[t + m];
        __syncthreads();
    }
    if (t == 0 && (size_t)out_size >= ZQ_ELEMS + 3) {
        float mean = (float)(sh[0] / (double)ZQ_ELEMS);
        float commit   = 0.25f * mean;
        float codebook = mean;
        out[ZQ_ELEMS + 0] = commit + codebook;
        out[ZQ_ELEMS + 1] = commit;
        out[ZQ_ELEMS + 2] = codebook;
    }
}

// ============================================================
extern "C" void kernel_launch(void* const* d_in, const int* in_sizes, int n_in,
                              void* d_out, int out_size) {
    const float* z   = (const float*)d_in[0];
    const float* emb = (const float*)d_in[1];
    if (n_in >= 2 && in_sizes[0] == KCODES * D && in_sizes[1] == NTOK * D) {
        z   = (const float*)d_in[1];
        emb = (const float*)d_in[0];
    }
    float* out = (float*)d_out;

    static bool attr_set = false;
    if (!attr_set) {
        cudaFuncSetAttribute(filter_kernel,
                             cudaFuncAttributeMaxDynamicSharedMemorySize, SMEM_TOTAL);
        attr_set = true;
    }

    esq_kernel  <<<KCODES / 128, 128>>>(emb);
    zsq_kernel  <<<NTOK / 256, 256>>>(z);
    filter_kernel<<<NTILES * NSPLIT, 256, SMEM_TOTAL>>>();
    rescore_kernel<<<NTOK / 8, 256>>>(z, emb);
    gather_kernel<<<GBLOCKS, 256>>>(z, emb, out, out_size);
    loss_kernel <<<1, 256>>>(out, out_size);
}

// round 15
// speedup vs baseline: 1.1988x; 1.1988x over previous
#include <cuda_runtime.h>
#include <cuda_bf16.h>
#include <cstdint>

#define D        256
#define KCODES   8192
#define NTOK     32768
#define CTAM     128
#define CTAN     128
#define NTILES   (NTOK / CTAM)       // 256
#define NCHUNKS  (KCODES / CTAN)     // 64
#define NSPLIT   4
#define CPS      (NCHUNKS / NSPLIT)  // 16
#define CAP      64
#define WINDOW   5.0e-4f
#define GBLOCKS  (NTOK / 8)
#define ZQ_ELEMS ((size_t)NTOK * D)
#define OUT_FULL (ZQ_ELEMS + 3 + NTOK)

// smem layout (bytes): padded bf16 rows, 264 elems = 528B (4-bank rotation)
#define SROW     528
#define ZS_BYTES (CTAM * SROW)                   // 67584
#define ES_OFF(b)  (ZS_BYTES + (b) * ZS_BYTES)   // two e buffers
#define ESQ_OFF(b) (3 * ZS_BYTES + (b) * 512)
#define SMEM_TOTAL (3 * ZS_BYTES + 1024)         // 203776

// ---- scratch (__device__ globals: sanctioned no-alloc path) ----
__device__ float          g_esq[KCODES];
__device__ float          g_zsq[NTOK];
__device__ unsigned short g_zbf[(size_t)NTOK * D];    // bf16 row-major
__device__ unsigned short g_ebf[(size_t)KCODES * D];  // bf16 row-major
__device__ int            g_ccount[NTOK];
__device__ int            g_cand[(size_t)NTOK * CAP];
__device__ int            g_bidx[NTOK];
__device__ float          g_part[GBLOCKS];

// ============================================================
// PTX helpers (baseline sm_80-level ISA only)
// ============================================================
__device__ __forceinline__ uint32_t smem_u32(const void* p) {
    uint32_t a;
    asm("{ .reg .u64 t; cvta.to.shared.u64 t, %1; cvt.u32.u64 %0, t; }" : "=r"(a) : "l"(p));
    return a;
}
__device__ __forceinline__ void cpa16(uint32_t dst, const void* src) {
    asm volatile("cp.async.cg.shared.global [%0], [%1], 16;" :: "r"(dst), "l"(src));
}
#define CP_COMMIT() asm volatile("cp.async.commit_group;" ::: "memory")
#define CP_WAIT0()  asm volatile("cp.async.wait_group 0;" ::: "memory")

__device__ __forceinline__ void ldsm4(uint32_t& r0, uint32_t& r1, uint32_t& r2, uint32_t& r3,
                                      uint32_t addr) {
    asm volatile("ldmatrix.sync.aligned.m8n8.x4.shared.b16 {%0,%1,%2,%3}, [%4];"
                 : "=r"(r0), "=r"(r1), "=r"(r2), "=r"(r3) : "r"(addr));
}
__device__ __forceinline__ void mma_bf16(float& c0, float& c1, float& c2, float& c3,
                                         uint32_t a0, uint32_t a1, uint32_t a2, uint32_t a3,
                                         uint32_t b0, uint32_t b1) {
    asm volatile("mma.sync.aligned.m16n8k16.row.col.f32.bf16.bf16.f32 "
                 "{%0,%1,%2,%3}, {%4,%5,%6,%7}, {%8,%9}, {%0,%1,%2,%3};"
                 : "+f"(c0), "+f"(c1), "+f"(c2), "+f"(c3)
                 : "r"(a0), "r"(a1), "r"(a2), "r"(a3), "r"(b0), "r"(b1));
}
__device__ __forceinline__ uint32_t pack_bf(float lo, float hi) {
    __nv_bfloat162 v = __floats2bfloat162_rn(lo, hi);
    return *reinterpret_cast<uint32_t*>(&v);
}

// ============================================================
// Kernel 0a: per-code ||e||^2 (bit-critical sequential chain)
//            FUSED with bf16 row conversion (same loads)
// ============================================================
__global__ void esq_kernel(const float* __restrict__ emb) {
    int k = blockIdx.x * blockDim.x + threadIdx.x;
    if (k >= KCODES) return;
    const float4* row = reinterpret_cast<const float4*>(emb + (size_t)k * D);
    uint4* dst = reinterpret_cast<uint4*>(g_ebf + (size_t)k * D);
    float s = 0.f;
#pragma unroll
    for (int i = 0; i < D / 8; ++i) {
        float4 a = row[2 * i];
        float4 b = row[2 * i + 1];
        s = fmaf(a.x, a.x, s); s = fmaf(a.y, a.y, s);
        s = fmaf(a.z, a.z, s); s = fmaf(a.w, a.w, s);
        s = fmaf(b.x, b.x, s); s = fmaf(b.y, b.y, s);
        s = fmaf(b.z, b.z, s); s = fmaf(b.w, b.w, s);
        dst[i] = make_uint4(pack_bf(a.x, a.y), pack_bf(a.z, a.w),
                            pack_bf(b.x, b.y), pack_bf(b.z, b.w));
    }
    g_esq[k] = s;
}

// ============================================================
// Kernel 0b: per-token ||z||^2 (bit-critical chain)
//            FUSED with bf16 row conversion + ccount zeroing
// ============================================================
__global__ void zsq_kernel(const float* __restrict__ z) {
    int n = blockIdx.x * blockDim.x + threadIdx.x;
    if (n >= NTOK) return;
    g_ccount[n] = 0;
    const float4* row = reinterpret_cast<const float4*>(z + (size_t)n * D);
    uint4* dst = reinterpret_cast<uint4*>(g_zbf + (size_t)n * D);
    float s = 0.f;
#pragma unroll 4
    for (int i = 0; i < D / 8; ++i) {
        float4 a = row[2 * i];
        float4 b = row[2 * i + 1];
        s = fmaf(a.x, a.x, s); s = fmaf(a.y, a.y, s);
        s = fmaf(a.z, a.z, s); s = fmaf(a.w, a.w, s);
        s = fmaf(b.x, b.x, s); s = fmaf(b.y, b.y, s);
        s = fmaf(b.z, b.z, s); s = fmaf(b.w, b.w, s);
        dst[i] = make_uint4(pack_bf(a.x, a.y), pack_bf(a.z, a.w),
                            pack_bf(b.x, b.y), pack_bf(b.z, b.w));
    }
    g_zsq[n] = s;
}

// ============================================================
// Kernel 1: bf16 mma.sync GEMM + running-min candidate filter.
//   EXACT R6/R11-validated shape (do not touch).
// ============================================================
__global__ __launch_bounds__(256, 1)
void filter_kernel() {
    extern __shared__ char smc[];
    const uint32_t sb = smem_u32(smc);
    const int tid = threadIdx.x, wid = tid >> 5, lane = tid & 31;
    const int tile = blockIdx.x >> 2;
    const int sp   = blockIdx.x & 3;
    const int g = lane >> 2, t4 = lane & 3;

    // ---- stage z tile + chunk 0 (+esq) via cp.async ----
    {
        const char* zsrc = (const char*)(g_zbf + (size_t)tile * CTAM * D);
#pragma unroll 4
        for (int i = tid; i < 4096; i += 256) {
            int r = i >> 5, c = i & 31;
            cpa16(sb + r * SROW + c * 16, zsrc + r * 512 + c * 16);
        }
        int chunk0 = sp * CPS;
        const char* esrc = (const char*)(g_ebf + (size_t)chunk0 * CTAN * D);
#pragma unroll 4
        for (int i = tid; i < 4096; i += 256) {
            int r = i >> 5, c = i & 31;
            cpa16(sb + ES_OFF(0) + r * SROW + c * 16, esrc + r * 512 + c * 16);
        }
        if (tid < 32) cpa16(sb + ESQ_OFF(0) + tid * 16,
                            (const char*)(g_esq + chunk0 * CTAN) + tid * 16);
        CP_COMMIT();
    }

    // per-lane fragment address bases (validated mapping)
    const uint32_t aBase = sb + (uint32_t)(wid * 16 + (lane & 15)) * SROW
                              + (uint32_t)((lane >> 4) * 8) * 2;
    const uint32_t bRowOff = (uint32_t)((lane & 7) + ((lane & 16) ? 8 : 0)) * SROW
                           + (uint32_t)((lane & 8) ? 8 : 0) * 2;

    const int tokg  = tile * CTAM + wid * 16 + g;
    const float zq0 = g_zsq[tokg];
    const float zq1 = g_zsq[tokg + 8];
    float run0 = 3.4e38f, run1 = 3.4e38f;

    for (int cl = 0; cl < CPS; ++cl) {
        const int cur = cl & 1;
        CP_WAIT0();
        __syncthreads();
        if (cl + 1 < CPS) {
            const int nxt = sp * CPS + cl + 1;
            const char* esrc = (const char*)(g_ebf + (size_t)nxt * CTAN * D);
#pragma unroll 4
            for (int i = tid; i < 4096; i += 256) {
                int r = i >> 5, c = i & 31;
                cpa16(sb + ES_OFF(1 - cur) + r * SROW + c * 16, esrc + r * 512 + c * 16);
            }
            if (tid < 32) cpa16(sb + ESQ_OFF(1 - cur) + tid * 16,
                                (const char*)(g_esq + nxt * CTAN) + tid * 16);
            CP_COMMIT();
        }

        float acc[16][4];
#pragma unroll
        for (int nb = 0; nb < 16; ++nb)
#pragma unroll
            for (int q = 0; q < 4; ++q) acc[nb][q] = 0.f;

        const uint32_t bBase = sb + ES_OFF(cur) + bRowOff;
#pragma unroll
        for (int ks = 0; ks < 16; ++ks) {
            uint32_t a0, a1, a2, a3;
            ldsm4(a0, a1, a2, a3, aBase + ks * 32);
#pragma unroll
            for (int nbp = 0; nbp < 8; ++nbp) {
                uint32_t b0, b1, b2, b3;
                ldsm4(b0, b1, b2, b3, bBase + nbp * (16 * SROW) + ks * 32);
                mma_bf16(acc[2 * nbp][0], acc[2 * nbp][1], acc[2 * nbp][2], acc[2 * nbp][3],
                         a0, a1, a2, a3, b0, b1);
                mma_bf16(acc[2 * nbp + 1][0], acc[2 * nbp + 1][1], acc[2 * nbp + 1][2], acc[2 * nbp + 1][3],
                         a0, a1, a2, a3, b2, b3);
            }
        }

        // ---- epilogue: approx scores, chunk-min, running-min, collect ----
        const int chunk = sp * CPS + cl;
        const int code0 = chunk * CTAN;
        const float* esqs = reinterpret_cast<const float*>(smc + ESQ_OFF(cur));
        float m0 = 3.4e38f, m1 = 3.4e38f;
#pragma unroll
        for (int nb = 0; nb < 16; ++nb) {
            float2 ee = *reinterpret_cast<const float2*>(esqs + nb * 8 + 2 * t4);
            float s00 = fmaf(-2.f, acc[nb][0], zq0 + ee.x);
            float s01 = fmaf(-2.f, acc[nb][1], zq0 + ee.y);
            float s10 = fmaf(-2.f, acc[nb][2], zq1 + ee.x);
            float s11 = fmaf(-2.f, acc[nb][3], zq1 + ee.y);
            acc[nb][0] = s00; acc[nb][1] = s01; acc[nb][2] = s10; acc[nb][3] = s11;
            m0 = fminf(m0, fminf(s00, s01));
            m1 = fminf(m1, fminf(s10, s11));
        }
        // quad-reduce (lanes sharing g)
        m0 = fminf(m0, __shfl_xor_sync(0xffffffffu, m0, 1));
        m0 = fminf(m0, __shfl_xor_sync(0xffffffffu, m0, 2));
        m1 = fminf(m1, __shfl_xor_sync(0xffffffffu, m1, 1));
        m1 = fminf(m1, __shfl_xor_sync(0xffffffffu, m1, 2));
        run0 = fminf(run0, m0);
        run1 = fminf(run1, m1);
        const float thr0 = run0 + WINDOW, thr1 = run1 + WINDOW;

#pragma unroll
        for (int nb = 0; nb < 16; ++nb) {
            const int cb = code0 + nb * 8 + 2 * t4;
            if (acc[nb][0] <= thr0) {
                int p = atomicAdd(&g_ccount[tokg], 1);
                if (p < CAP) g_cand[(size_t)tokg * CAP + p] = cb;
            }
            if (acc[nb][1] <= thr0) {
                int p = atomicAdd(&g_ccount[tokg], 1);
                if (p < CAP) g_cand[(size_t)tokg * CAP + p] = cb + 1;
            }
            if (acc[nb][2] <= thr1) {
                int p = atomicAdd(&g_ccount[tokg + 8], 1);
                if (p < CAP) g_cand[(size_t)(tokg + 8) * CAP + p] = cb;
            }
            if (acc[nb][3] <= thr1) {
                int p = atomicAdd(&g_ccount[tokg + 8], 1);
                if (p < CAP) g_cand[(size_t)(tokg + 8) * CAP + p] = cb + 1;
            }
        }
        __syncthreads();   // all warps done with buf[cur] before it is refilled
    }
}

// ============================================================
// Kernel 2: exact rescore v3 — one 32-thread block per token.
//   Candidate e-rows staged to smem COALESCED (codes via shfl),
//   then each lane runs the bit-exact sequential fmaf chain from
//   smem. Numerics identical to validated path; only the memory
//   access pattern changes (8 wavefronts/row vs ~2048).
// ============================================================
__global__ void rescore_kernel(const float* __restrict__ z, const float* __restrict__ emb) {
    __shared__ float4 sz[64];         // z row (1 KB)
    __shared__ float4 se[32][65];     // 32 e-rows, pad 1 float4 -> conflict-free phases

    const int n = blockIdx.x;
    const int lane = threadIdx.x;     // 32 threads
    const int cnt = g_ccount[n];

    // fast path: single candidate IS the argmin
    if (cnt == 1) {
        if (lane == 0) g_bidx[n] = g_cand[(size_t)n * CAP];
        return;
    }

    const float zq = g_zsq[n];
    float bs = 3.4e38f; int bi = 0x7fffffff;

    if (cnt <= CAP) {
        // stage z row (coalesced)
        const float4* zr = reinterpret_cast<const float4*>(z + (size_t)n * D);
        sz[lane]      = zr[lane];
        sz[lane + 32] = zr[lane + 32];

        for (int base = 0; base < cnt; base += 32) {
            const int rmax = min(32, cnt - base);
            int code = 0;
            if (base + lane < cnt) code = g_cand[(size_t)n * CAP + base + lane];

            // stage rmax candidate rows, coalesced (2 float4 per lane per row)
            for (int r = 0; r < rmax; ++r) {
                int c = __shfl_sync(0xffffffffu, code, r);
                const float4* er = reinterpret_cast<const float4*>(emb + (size_t)c * D);
                se[r][lane]      = er[lane];
                se[r][lane + 32] = er[lane + 32];
            }
            __syncwarp();

            if (lane < rmax) {
                float acc = 0.f;
#pragma unroll 8
                for (int i = 0; i < 64; ++i) {
                    float4 a = sz[i];           // broadcast
                    float4 b = se[lane][i];
                    acc = fmaf(a.x, b.x, acc); acc = fmaf(a.y, b.y, acc);
                    acc = fmaf(a.z, b.z, acc); acc = fmaf(a.w, b.w, acc);
                }
                float t1 = __fadd_rn(zq, g_esq[code]);
                float s  = __fadd_rn(t1, -2.0f * acc);
                if (s < bs || (s == bs && code < bi)) { bs = s; bi = code; }
            }
            __syncwarp();
        }
    } else {
        // overflow fallback (never observed): scalar scan, low regs
        const float4* zr = reinterpret_cast<const float4*>(z + (size_t)n * D);
#pragma unroll 1
        for (int code = lane; code < KCODES; code += 32) {
            const float4* er = reinterpret_cast<const float4*>(emb + (size_t)code * D);
            float acc = 0.f;
#pragma unroll 8
            for (int i = 0; i < D / 4; ++i) {
                float4 a = zr[i], b = er[i];
                acc = fmaf(a.x, b.x, acc); acc = fmaf(a.y, b.y, acc);
                acc = fmaf(a.z, b.z, acc); acc = fmaf(a.w, b.w, acc);
            }
            float t1 = __fadd_rn(zq, g_esq[code]);
            float s  = __fadd_rn(t1, -2.0f * acc);
            if (s < bs) { bs = s; bi = code; }   // ascending codes: first-min kept
        }
    }

#pragma unroll
    for (int m = 16; m >= 1; m >>= 1) {
        float ov = __shfl_xor_sync(0xffffffffu, bs, m);
        int   oi = __shfl_xor_sync(0xffffffffu, bi, m);
        if (ov < bs || (ov == bs && oi < bi)) { bs = ov; bi = oi; }
    }
    if (lane == 0) g_bidx[n] = bi;
}

// ============================================================
// Kernel 3: gather + straight-through output + loss partials
//   exact replication of fl(z + fl(e - z))
// ============================================================
__global__ void gather_kernel(const float* __restrict__ z, const float* __restrict__ emb,
                              float* __restrict__ out, int out_size) {
    __shared__ float wsum[8];
    const int lane = threadIdx.x & 31;
    const int wib  = threadIdx.x >> 5;
    const int n    = blockIdx.x * 8 + wib;

    const int idx = g_bidx[n];
    const float4* zr = reinterpret_cast<const float4*>(z   + (size_t)n   * D);
    const float4* er = reinterpret_cast<const float4*>(emb + (size_t)idx * D);
    float4* orow = reinterpret_cast<float4*>(out + (size_t)n * D);

    float ss = 0.f;
#pragma unroll
    for (int i = lane; i < D / 4; i += 32) {
        float4 zv = zr[i], ev = er[i], df, ov;
        df.x = ev.x - zv.x; df.y = ev.y - zv.y; df.z = ev.z - zv.z; df.w = ev.w - zv.w;
        ov.x = zv.x + df.x; ov.y = zv.y + df.y; ov.z = zv.z + df.z; ov.w = zv.w + df.w;
        ss = fmaf(df.x, df.x, ss); ss = fmaf(df.y, df.y, ss);
        ss = fmaf(df.z, df.z, ss); ss = fmaf(df.w, df.w, ss);
        if ((size_t)out_size >= ZQ_ELEMS) orow[i] = ov;
    }
#pragma unroll
    for (int m = 16; m >= 1; m >>= 1) ss += __shfl_xor_sync(0xffffffffu, ss, m);
    if (lane == 0) wsum[wib] = ss;
    __syncthreads();
    if (threadIdx.x == 0) {
        float t = 0.f;
#pragma unroll
        for (int w = 0; w < 8; ++w) t += wsum[w];
        g_part[blockIdx.x] = t;
    }
    if (lane == 0 && (size_t)out_size >= OUT_FULL)
        out[ZQ_ELEMS + 3 + n] = (float)idx;
}

// ============================================================
// Kernel 4: deterministic loss finalize (double accumulation)
// ============================================================
__global__ void loss_kernel(float* __restrict__ out, int out_size) {
    __shared__ double sh[256];
    const int t = threadIdx.x;
    double s = 0.0;
#pragma unroll 4
    for (int i = t * (GBLOCKS / 256); i < (t + 1) * (GBLOCKS / 256); ++i)
        s += (double)g_part[i];
    sh[t] = s;
    __syncthreads();
    for (int m = 128; m >= 1; m >>= 1) {
        if (t < m) sh[t] += sh[t + m];
        __syncthreads();
    }
    if (t == 0 && (size_t)out_size >= ZQ_ELEMS + 3) {
        float mean = (float)(sh[0] / (double)ZQ_ELEMS);
        float commit   = 0.25f * mean;
        float codebook = mean;
        out[ZQ_ELEMS + 0] = commit + codebook;
        out[ZQ_ELEMS + 1] = commit;
        out[ZQ_ELEMS + 2] = codebook;
    }
}

// ============================================================
extern "C" void kernel_launch(void* const* d_in, const int* in_sizes, int n_in,
                              void* d_out, int out_size) {
    const float* z   = (const float*)d_in[0];
    const float* emb = (const float*)d_in[1];
    if (n_in >= 2 && in_sizes[0] == KCODES * D && in_sizes[1] == NTOK * D) {
        z   = (const float*)d_in[1];
        emb = (const float*)d_in[0];
    }
    float* out = (float*)d_out;

    static bool attr_set = false;
    if (!attr_set) {
        cudaFuncSetAttribute(filter_kernel,
                             cudaFuncAttributeMaxDynamicSharedMemorySize, SMEM_TOTAL);
        attr_set = true;
    }

    esq_kernel  <<<KCODES / 128, 128>>>(emb);
    zsq_kernel  <<<NTOK / 256, 256>>>(z);
    filter_kernel<<<NTILES * NSPLIT, 256, SMEM_TOTAL>>>();
    rescore_kernel<<<NTOK, 32>>>(z, emb);
    gather_kernel<<<GBLOCKS, 256>>>(z, emb, out, out_size);
    loss_kernel <<<1, 256>>>(out, out_size);
}

// round 16
// speedup vs baseline: 1.2585x; 1.0498x over previous
#include <cuda_runtime.h>
#include <cuda_bf16.h>
#include <cstdint>

#define D        256
#define KCODES   8192
#define NTOK     32768
#define CTAM     128
#define CTAN     128
#define NTILES   (NTOK / CTAM)       // 256
#define NCHUNKS  (KCODES / CTAN)     // 64
#define NSPLIT   4
#define CPS      (NCHUNKS / NSPLIT)  // 16
#define CAP      64
#define WINDOW   5.0e-4f
#define GBLOCKS  (NTOK / 8)
#define ZQ_ELEMS ((size_t)NTOK * D)
#define OUT_FULL (ZQ_ELEMS + 3 + NTOK)

// smem layout (bytes): padded bf16 rows, 264 elems = 528B (4-bank rotation)
#define SROW     528
#define ZS_BYTES (CTAM * SROW)                   // 67584
#define ES_OFF(b)  (ZS_BYTES + (b) * ZS_BYTES)   // two e buffers
#define ESQ_OFF(b) (3 * ZS_BYTES + (b) * 512)
#define SMEM_TOTAL (3 * ZS_BYTES + 1024)         // 203776

// ---- scratch (__device__ globals: sanctioned no-alloc path) ----
__device__ float          g_esq[KCODES];
__device__ float          g_zsq[NTOK];
__device__ unsigned short g_zbf[(size_t)NTOK * D];    // bf16 row-major
__device__ unsigned short g_ebf[(size_t)KCODES * D];  // bf16 row-major
__device__ int            g_ccount[NTOK];
__device__ int            g_cand[(size_t)NTOK * CAP];
__device__ int            g_bidx[NTOK];
__device__ float          g_part[GBLOCKS];

// ============================================================
// PTX helpers (baseline sm_80-level ISA only)
// ============================================================
__device__ __forceinline__ uint32_t smem_u32(const void* p) {
    uint32_t a;
    asm("{ .reg .u64 t; cvta.to.shared.u64 t, %1; cvt.u32.u64 %0, t; }" : "=r"(a) : "l"(p));
    return a;
}
__device__ __forceinline__ void cpa16(uint32_t dst, const void* src) {
    asm volatile("cp.async.cg.shared.global [%0], [%1], 16;" :: "r"(dst), "l"(src));
}
#define CP_COMMIT() asm volatile("cp.async.commit_group;" ::: "memory")
#define CP_WAIT0()  asm volatile("cp.async.wait_group 0;" ::: "memory")

__device__ __forceinline__ void ldsm4(uint32_t& r0, uint32_t& r1, uint32_t& r2, uint32_t& r3,
                                      uint32_t addr) {
    asm volatile("ldmatrix.sync.aligned.m8n8.x4.shared.b16 {%0,%1,%2,%3}, [%4];"
                 : "=r"(r0), "=r"(r1), "=r"(r2), "=r"(r3) : "r"(addr));
}
__device__ __forceinline__ void mma_bf16(float& c0, float& c1, float& c2, float& c3,
                                         uint32_t a0, uint32_t a1, uint32_t a2, uint32_t a3,
                                         uint32_t b0, uint32_t b1) {
    asm volatile("mma.sync.aligned.m16n8k16.row.col.f32.bf16.bf16.f32 "
                 "{%0,%1,%2,%3}, {%4,%5,%6,%7}, {%8,%9}, {%0,%1,%2,%3};"
                 : "+f"(c0), "+f"(c1), "+f"(c2), "+f"(c3)
                 : "r"(a0), "r"(a1), "r"(a2), "r"(a3), "r"(b0), "r"(b1));
}
__device__ __forceinline__ uint32_t pack_bf(float lo, float hi) {
    __nv_bfloat162 v = __floats2bfloat162_rn(lo, hi);
    return *reinterpret_cast<uint32_t*>(&v);
}

// ============================================================
// Kernel 0a: per-code ||e||^2 (bit-critical sequential chain)
//            FUSED with bf16 row conversion (same loads)
// ============================================================
__global__ void esq_kernel(const float* __restrict__ emb) {
    int k = blockIdx.x * blockDim.x + threadIdx.x;
    if (k >= KCODES) return;
    const float4* row = reinterpret_cast<const float4*>(emb + (size_t)k * D);
    uint4* dst = reinterpret_cast<uint4*>(g_ebf + (size_t)k * D);
    float s = 0.f;
#pragma unroll
    for (int i = 0; i < D / 8; ++i) {
        float4 a = row[2 * i];
        float4 b = row[2 * i + 1];
        s = fmaf(a.x, a.x, s); s = fmaf(a.y, a.y, s);
        s = fmaf(a.z, a.z, s); s = fmaf(a.w, a.w, s);
        s = fmaf(b.x, b.x, s); s = fmaf(b.y, b.y, s);
        s = fmaf(b.z, b.z, s); s = fmaf(b.w, b.w, s);
        dst[i] = make_uint4(pack_bf(a.x, a.y), pack_bf(a.z, a.w),
                            pack_bf(b.x, b.y), pack_bf(b.z, b.w));
    }
    g_esq[k] = s;
}

// ============================================================
// Kernel 0b: per-token ||z||^2 (bit-critical chain)
//            FUSED with bf16 row conversion + ccount zeroing
// ============================================================
__global__ void zsq_kernel(const float* __restrict__ z) {
    int n = blockIdx.x * blockDim.x + threadIdx.x;
    if (n >= NTOK) return;
    g_ccount[n] = 0;
    const float4* row = reinterpret_cast<const float4*>(z + (size_t)n * D);
    uint4* dst = reinterpret_cast<uint4*>(g_zbf + (size_t)n * D);
    float s = 0.f;
#pragma unroll 4
    for (int i = 0; i < D / 8; ++i) {
        float4 a = row[2 * i];
        float4 b = row[2 * i + 1];
        s = fmaf(a.x, a.x, s); s = fmaf(a.y, a.y, s);
        s = fmaf(a.z, a.z, s); s = fmaf(a.w, a.w, s);
        s = fmaf(b.x, b.x, s); s = fmaf(b.y, b.y, s);
        s = fmaf(b.z, b.z, s); s = fmaf(b.w, b.w, s);
        dst[i] = make_uint4(pack_bf(a.x, a.y), pack_bf(a.z, a.w),
                            pack_bf(b.x, b.y), pack_bf(b.z, b.w));
    }
    g_zsq[n] = s;
}

// ============================================================
// Kernel 1: bf16 mma.sync GEMM + running-min candidate filter.
//   EXACT R6/R11-validated shape (do not touch).
// ============================================================
__global__ __launch_bounds__(256, 1)
void filter_kernel() {
    extern __shared__ char smc[];
    const uint32_t sb = smem_u32(smc);
    const int tid = threadIdx.x, wid = tid >> 5, lane = tid & 31;
    const int tile = blockIdx.x >> 2;
    const int sp   = blockIdx.x & 3;
    const int g = lane >> 2, t4 = lane & 3;

    // ---- stage z tile + chunk 0 (+esq) via cp.async ----
    {
        const char* zsrc = (const char*)(g_zbf + (size_t)tile * CTAM * D);
#pragma unroll 4
        for (int i = tid; i < 4096; i += 256) {
            int r = i >> 5, c = i & 31;
            cpa16(sb + r * SROW + c * 16, zsrc + r * 512 + c * 16);
        }
        int chunk0 = sp * CPS;
        const char* esrc = (const char*)(g_ebf + (size_t)chunk0 * CTAN * D);
#pragma unroll 4
        for (int i = tid; i < 4096; i += 256) {
            int r = i >> 5, c = i & 31;
            cpa16(sb + ES_OFF(0) + r * SROW + c * 16, esrc + r * 512 + c * 16);
        }
        if (tid < 32) cpa16(sb + ESQ_OFF(0) + tid * 16,
                            (const char*)(g_esq + chunk0 * CTAN) + tid * 16);
        CP_COMMIT();
    }

    // per-lane fragment address bases (validated mapping)
    const uint32_t aBase = sb + (uint32_t)(wid * 16 + (lane & 15)) * SROW
                              + (uint32_t)((lane >> 4) * 8) * 2;
    const uint32_t bRowOff = (uint32_t)((lane & 7) + ((lane & 16) ? 8 : 0)) * SROW
                           + (uint32_t)((lane & 8) ? 8 : 0) * 2;

    const int tokg  = tile * CTAM + wid * 16 + g;
    const float zq0 = g_zsq[tokg];
    const float zq1 = g_zsq[tokg + 8];
    float run0 = 3.4e38f, run1 = 3.4e38f;

    for (int cl = 0; cl < CPS; ++cl) {
        const int cur = cl & 1;
        CP_WAIT0();
        __syncthreads();
        if (cl + 1 < CPS) {
            const int nxt = sp * CPS + cl + 1;
            const char* esrc = (const char*)(g_ebf + (size_t)nxt * CTAN * D);
#pragma unroll 4
            for (int i = tid; i < 4096; i += 256) {
                int r = i >> 5, c = i & 31;
                cpa16(sb + ES_OFF(1 - cur) + r * SROW + c * 16, esrc + r * 512 + c * 16);
            }
            if (tid < 32) cpa16(sb + ESQ_OFF(1 - cur) + tid * 16,
                                (const char*)(g_esq + nxt * CTAN) + tid * 16);
            CP_COMMIT();
        }

        float acc[16][4];
#pragma unroll
        for (int nb = 0; nb < 16; ++nb)
#pragma unroll
            for (int q = 0; q < 4; ++q) acc[nb][q] = 0.f;

        const uint32_t bBase = sb + ES_OFF(cur) + bRowOff;
#pragma unroll
        for (int ks = 0; ks < 16; ++ks) {
            uint32_t a0, a1, a2, a3;
            ldsm4(a0, a1, a2, a3, aBase + ks * 32);
#pragma unroll
            for (int nbp = 0; nbp < 8; ++nbp) {
                uint32_t b0, b1, b2, b3;
                ldsm4(b0, b1, b2, b3, bBase + nbp * (16 * SROW) + ks * 32);
                mma_bf16(acc[2 * nbp][0], acc[2 * nbp][1], acc[2 * nbp][2], acc[2 * nbp][3],
                         a0, a1, a2, a3, b0, b1);
                mma_bf16(acc[2 * nbp + 1][0], acc[2 * nbp + 1][1], acc[2 * nbp + 1][2], acc[2 * nbp + 1][3],
                         a0, a1, a2, a3, b2, b3);
            }
        }

        // ---- epilogue: approx scores, chunk-min, running-min, collect ----
        const int chunk = sp * CPS + cl;
        const int code0 = chunk * CTAN;
        const float* esqs = reinterpret_cast<const float*>(smc + ESQ_OFF(cur));
        float m0 = 3.4e38f, m1 = 3.4e38f;
#pragma unroll
        for (int nb = 0; nb < 16; ++nb) {
            float2 ee = *reinterpret_cast<const float2*>(esqs + nb * 8 + 2 * t4);
            float s00 = fmaf(-2.f, acc[nb][0], zq0 + ee.x);
            float s01 = fmaf(-2.f, acc[nb][1], zq0 + ee.y);
            float s10 = fmaf(-2.f, acc[nb][2], zq1 + ee.x);
            float s11 = fmaf(-2.f, acc[nb][3], zq1 + ee.y);
            acc[nb][0] = s00; acc[nb][1] = s01; acc[nb][2] = s10; acc[nb][3] = s11;
            m0 = fminf(m0, fminf(s00, s01));
            m1 = fminf(m1, fminf(s10, s11));
        }
        // quad-reduce (lanes sharing g)
        m0 = fminf(m0, __shfl_xor_sync(0xffffffffu, m0, 1));
        m0 = fminf(m0, __shfl_xor_sync(0xffffffffu, m0, 2));
        m1 = fminf(m1, __shfl_xor_sync(0xffffffffu, m1, 1));
        m1 = fminf(m1, __shfl_xor_sync(0xffffffffu, m1, 2));
        run0 = fminf(run0, m0);
        run1 = fminf(run1, m1);
        const float thr0 = run0 + WINDOW, thr1 = run1 + WINDOW;

#pragma unroll
        for (int nb = 0; nb < 16; ++nb) {
            const int cb = code0 + nb * 8 + 2 * t4;
            if (acc[nb][0] <= thr0) {
                int p = atomicAdd(&g_ccount[tokg], 1);
                if (p < CAP) g_cand[(size_t)tokg * CAP + p] = cb;
            }
            if (acc[nb][1] <= thr0) {
                int p = atomicAdd(&g_ccount[tokg], 1);
                if (p < CAP) g_cand[(size_t)tokg * CAP + p] = cb + 1;
            }
            if (acc[nb][2] <= thr1) {
                int p = atomicAdd(&g_ccount[tokg + 8], 1);
                if (p < CAP) g_cand[(size_t)(tokg + 8) * CAP + p] = cb;
            }
            if (acc[nb][3] <= thr1) {
                int p = atomicAdd(&g_ccount[tokg + 8], 1);
                if (p < CAP) g_cand[(size_t)(tokg + 8) * CAP + p] = cb + 1;
            }
        }
        __syncthreads();   // all warps done with buf[cur] before it is refilled
    }
}

// ============================================================
// Kernel 2: exact rescore v4 — one 32-thread block per token.
//   Same validated coalesced-staging scheme as v3 but staging
//   rounds of 8 rows (se[8][65], 9.3 KB total) so ~24 blocks/SM
//   fit instead of 6. Numerics byte-identical.
// ============================================================
__global__ __launch_bounds__(32)
void rescore_kernel(const float* __restrict__ z, const float* __restrict__ emb) {
    __shared__ float4 sz[64];         // z row (1 KB)
    __shared__ float4 se[8][65];      // 8 e-rows, pad 1 float4 (8.3 KB)

    const int n = blockIdx.x;
    const int lane = threadIdx.x;     // 32 threads
    const int cnt = g_ccount[n];

    // fast path: single candidate IS the argmin
    if (cnt == 1) {
        if (lane == 0) g_bidx[n] = g_cand[(size_t)n * CAP];
        return;
    }

    const float zq = g_zsq[n];
    float bs = 3.4e38f; int bi = 0x7fffffff;

    if (cnt <= CAP) {
        // stage z row (coalesced)
        const float4* zr = reinterpret_cast<const float4*>(z + (size_t)n * D);
        sz[lane]      = zr[lane];
        sz[lane + 32] = zr[lane + 32];

        for (int base = 0; base < cnt; base += 8) {
            const int rmax = min(8, cnt - base);
            int code = 0;
            if (lane < rmax) code = g_cand[(size_t)n * CAP + base + lane];

            // stage rmax candidate rows, coalesced (2 float4 per lane per row)
            for (int r = 0; r < rmax; ++r) {
                int c = __shfl_sync(0xffffffffu, code, r);
                const float4* er = reinterpret_cast<const float4*>(emb + (size_t)c * D);
                se[r][lane]      = er[lane];
                se[r][lane + 32] = er[lane + 32];
            }
            __syncwarp();

            if (lane < rmax) {
                float acc = 0.f;
#pragma unroll 8
                for (int i = 0; i < 64; ++i) {
                    float4 a = sz[i];           // broadcast
                    float4 b = se[lane][i];
                    acc = fmaf(a.x, b.x, acc); acc = fmaf(a.y, b.y, acc);
                    acc = fmaf(a.z, b.z, acc); acc = fmaf(a.w, b.w, acc);
                }
                float t1 = __fadd_rn(zq, g_esq[code]);
                float s  = __fadd_rn(t1, -2.0f * acc);
                if (s < bs || (s == bs && code < bi)) { bs = s; bi = code; }
            }
            __syncwarp();
        }
    } else {
        // overflow fallback (never observed): scalar scan, low regs
        const float4* zr = reinterpret_cast<const float4*>(z + (size_t)n * D);
#pragma unroll 1
        for (int code = lane; code < KCODES; code += 32) {
            const float4* er = reinterpret_cast<const float4*>(emb + (size_t)code * D);
            float acc = 0.f;
#pragma unroll 8
            for (int i = 0; i < D / 4; ++i) {
                float4 a = zr[i], b = er[i];
                acc = fmaf(a.x, b.x, acc); acc = fmaf(a.y, b.y, acc);
                acc = fmaf(a.z, b.z, acc); acc = fmaf(a.w, b.w, acc);
            }
            float t1 = __fadd_rn(zq, g_esq[code]);
            float s  = __fadd_rn(t1, -2.0f * acc);
            if (s < bs) { bs = s; bi = code; }   // ascending codes: first-min kept
        }
    }

#pragma unroll
    for (int m = 16; m >= 1; m >>= 1) {
        float ov = __shfl_xor_sync(0xffffffffu, bs, m);
        int   oi = __shfl_xor_sync(0xffffffffu, bi, m);
        if (ov < bs || (ov == bs && oi < bi)) { bs = ov; bi = oi; }
    }
    if (lane == 0) g_bidx[n] = bi;
}

// ============================================================
// Kernel 3: gather + straight-through output + loss partials
//   exact replication of fl(z + fl(e - z))
// ============================================================
__global__ void gather_kernel(const float* __restrict__ z, const float* __restrict__ emb,
                              float* __restrict__ out, int out_size) {
    __shared__ float wsum[8];
    const int lane = threadIdx.x & 31;
    const int wib  = threadIdx.x >> 5;
    const int n    = blockIdx.x * 8 + wib;

    const int idx = g_bidx[n];
    const float4* zr = reinterpret_cast<const float4*>(z   + (size_t)n   * D);
    const float4* er = reinterpret_cast<const float4*>(emb + (size_t)idx * D);
    float4* orow = reinterpret_cast<float4*>(out + (size_t)n * D);

    float ss = 0.f;
#pragma unroll
    for (int i = lane; i < D / 4; i += 32) {
        float4 zv = zr[i], ev = er[i], df, ov;
        df.x = ev.x - zv.x; df.y = ev.y - zv.y; df.z = ev.z - zv.z; df.w = ev.w - zv.w;
        ov.x = zv.x + df.x; ov.y = zv.y + df.y; ov.z = zv.z + df.z; ov.w = zv.w + df.w;
        ss = fmaf(df.x, df.x, ss); ss = fmaf(df.y, df.y, ss);
        ss = fmaf(df.z, df.z, ss); ss = fmaf(df.w, df.w, ss);
        if ((size_t)out_size >= ZQ_ELEMS) orow[i] = ov;
    }
#pragma unroll
    for (int m = 16; m >= 1; m >>= 1) ss += __shfl_xor_sync(0xffffffffu, ss, m);
    if (lane == 0) wsum[wib] = ss;
    __syncthreads();
    if (threadIdx.x == 0) {
        float t = 0.f;
#pragma unroll
        for (int w = 0; w < 8; ++w) t += wsum[w];
        g_part[blockIdx.x] = t;
    }
    if (lane == 0 && (size_t)out_size >= OUT_FULL)
        out[ZQ_ELEMS + 3 + n] = (float)idx;
}

// ============================================================
// Kernel 4: deterministic loss finalize (double accumulation)
// ============================================================
__global__ void loss_kernel(float* __restrict__ out, int out_size) {
    __shared__ double sh[256];
    const int t = threadIdx.x;
    double s = 0.0;
#pragma unroll 4
    for (int i = t * (GBLOCKS / 256); i < (t + 1) * (GBLOCKS / 256); ++i)
        s += (double)g_part[i];
    sh[t] = s;
    __syncthreads();
    for (int m = 128; m >= 1; m >>= 1) {
        if (t < m) sh[t] += sh[t + m];
        __syncthreads();
    }
    if (t == 0 && (size_t)out_size >= ZQ_ELEMS + 3) {
        float mean = (float)(sh[0] / (double)ZQ_ELEMS);
        float commit   = 0.25f * mean;
        float codebook = mean;
        out[ZQ_ELEMS + 0] = commit + codebook;
        out[ZQ_ELEMS + 1] = commit;
        out[ZQ_ELEMS + 2] = codebook;
    }
}

// ============================================================
extern "C" void kernel_launch(void* const* d_in, const int* in_sizes, int n_in,
                              void* d_out, int out_size) {
    const float* z   = (const float*)d_in[0];
    const float* emb = (const float*)d_in[1];
    if (n_in >= 2 && in_sizes[0] == KCODES * D && in_sizes[1] == NTOK * D) {
        z   = (const float*)d_in[1];
        emb = (const float*)d_in[0];
    }
    float* out = (float*)d_out;

    static bool attr_set = false;
    if (!attr_set) {
        cudaFuncSetAttribute(filter_kernel,
                             cudaFuncAttributeMaxDynamicSharedMemorySize, SMEM_TOTAL);
        attr_set = true;
    }

    esq_kernel  <<<KCODES / 128, 128>>>(emb);
    zsq_kernel  <<<NTOK / 256, 256>>>(z);
    filter_kernel<<<NTILES * NSPLIT, 256, SMEM_TOTAL>>>();
    rescore_kernel<<<NTOK, 32>>>(z, emb);
    gather_kernel<<<GBLOCKS, 256>>>(z, emb, out, out_size);
    loss_kernel <<<1, 256>>>(out, out_size);
}